// round 13
// baseline (speedup 1.0000x reference)
#include <cuda_runtime.h>
#include <cuda_bf16.h>
#include <cstdint>

// y = (x + 2) * 3 / 2 == fmaf(1.5f, x, 3.0f)
// R13: async-proxy path probe — cp.async.bulk (gmem->smem), FMA in smem,
// cp.async.bulk (smem->gmem). Tests whether bulk full-line transfers beat
// the generic LSU path at the DRAM controller (all LSU-path variants
// plateaued at ~81% DRAM cycles across R1-R12).

constexpr int THREADS = 512;
constexpr int TILE_FLOATS = 4096;                 // 16 KB per block
constexpr int TILE_BYTES = TILE_FLOATS * 4;
constexpr int F4_PER_THREAD = TILE_FLOATS / 4 / THREADS;  // = 2

__device__ __forceinline__ uint32_t smem_u32(const void* p) {
    uint32_t a;
    asm("{ .reg .u64 t; cvta.to.shared.u64 t, %1; cvt.u32.u64 %0, t; }"
        : "=r"(a) : "l"(p));
    return a;
}

__global__ void __launch_bounds__(THREADS) fma_bulk_kernel(
    const float* __restrict__ in, float* __restrict__ out)
{
    __shared__ alignas(128) float tile[TILE_FLOATS];
    __shared__ alignas(8) unsigned long long mbar;

    const uint32_t s_tile = smem_u32(tile);
    const uint32_t s_mbar = smem_u32(&mbar);

    const float* gsrc = in + (size_t)blockIdx.x * TILE_FLOATS;
    float* gdst = out + (size_t)blockIdx.x * TILE_FLOATS;

    if (threadIdx.x == 0) {
        asm volatile("mbarrier.init.shared.b64 [%0], 1;" :: "r"(s_mbar) : "memory");
    }
    __syncthreads();

    if (threadIdx.x == 0) {
        asm volatile("mbarrier.arrive.expect_tx.shared.b64 _, [%0], %1;"
                     :: "r"(s_mbar), "r"(TILE_BYTES) : "memory");
        asm volatile(
            "cp.async.bulk.shared::cta.global.mbarrier::complete_tx::bytes "
            "[%0], [%1], %2, [%3];"
            :: "r"(s_tile), "l"(gsrc), "r"(TILE_BYTES), "r"(s_mbar) : "memory");
    }

    // All threads wait for the tile (phase 0).
    {
        uint32_t done;
        asm volatile(
            "{\n\t.reg .pred p;\n\t"
            "mbarrier.try_wait.parity.acquire.cta.shared::cta.b64 p, [%1], 0;\n\t"
            "selp.b32 %0, 1, 0, p;\n\t}"
            : "=r"(done) : "r"(s_mbar) : "memory");
        if (!done) {
            asm volatile(
                "{\n\t.reg .pred P1;\n\t"
                "WL_%=:\n\t"
                "mbarrier.try_wait.parity.acquire.cta.shared::cta.b64 P1, [%0], 0, 0x989680;\n\t"
                "@P1 bra.uni WD_%=;\n\t"
                "bra.uni WL_%=;\n\t"
                "WD_%=:\n\t}"
                :: "r"(s_mbar) : "memory");
        }
    }

    // FMA in place.
    float4* t4 = reinterpret_cast<float4*>(tile);
#pragma unroll
    for (int k = 0; k < F4_PER_THREAD; k++) {
        unsigned i = threadIdx.x + k * THREADS;
        float4 v = t4[i];
        v.x = fmaf(1.5f, v.x, 3.0f);
        v.y = fmaf(1.5f, v.y, 3.0f);
        v.z = fmaf(1.5f, v.z, 3.0f);
        v.w = fmaf(1.5f, v.w, 3.0f);
        t4[i] = v;
    }
    __syncthreads();

    if (threadIdx.x == 0) {
        asm volatile("fence.proxy.async.shared::cta;" ::: "memory");
        asm volatile(
            "cp.async.bulk.global.shared::cta.bulk_group [%0], [%1], %2;"
            :: "l"(gdst), "r"(s_tile), "r"(TILE_BYTES) : "memory");
        asm volatile("cp.async.bulk.commit_group;" ::: "memory");
        // Must complete before block exit (smem is read asynchronously).
        asm volatile("cp.async.bulk.wait_group 0;" ::: "memory");
    }
}

// Generic remainder kernel (element granularity, any size).
__global__ void fma_tail_kernel(const float* __restrict__ in,
                                float* __restrict__ out,
                                long long start, long long n)
{
    long long i = start + (long long)blockIdx.x * blockDim.x + threadIdx.x;
    if (i < n) out[i] = fmaf(1.5f, in[i], 3.0f);
}

extern "C" void kernel_launch(void* const* d_in, const int* in_sizes, int n_in,
                              void* d_out, int out_size)
{
    const float* in = (const float*)d_in[0];
    float* out = (float*)d_out;
    long long n = (long long)in_sizes[0];

    long long full_blocks = n / TILE_FLOATS;
    if (full_blocks > 0) {
        fma_bulk_kernel<<<(unsigned)full_blocks, THREADS>>>(in, out);
    }
    long long done = full_blocks * (long long)TILE_FLOATS;
    long long tail = n - done;
    if (tail > 0) {
        fma_tail_kernel<<<(unsigned)((tail + 255) / 256), 256>>>(
            in, out, done, n);
    }
}

// round 14
// speedup vs baseline: 1.0043x; 1.0043x over previous
#include <cuda_runtime.h>
#include <cuda_bf16.h>

// y = (x + 2) * 3 / 2 == fmaf(1.5f, x, 3.0f)
//
// FINAL: HBM-bound streaming kernel at the measured GB300 r+w ceiling
// (~74-75us kernel, ~6.9 TB/s application traffic, ~81% of peak DRAM
// cycles). Config space exhaustively swept R1-R13 with
// predict->measure->post-mortem:
//   VPT {1,2,4,8,16}            -> saturated at >=4-wide in-flight bytes
//   128/256-bit vector ld/st    -> equal
//   block {256,512}             -> equal
//   tile {16,32,64} KB          -> equal
//   flat vs persistent grid     -> flat wins (HW work-steal > static bind)
//   load/store sw pipelining    -> equal
//   .cs vs .wt store policy     -> equal
//   occupancy 30-79%            -> non-binding
//   LSU path vs cp.async.bulk   -> bulk 3% slower (sync overhead; DRAM
//                                  ceiling path-independent, as the B300
//                                  LTS-cap measurements predicted)
// Binding constraint: HBM3e bus turnaround + refresh. Traffic is minimal
// (one read + one write per element, no reuse exists for elementwise op).
//
// Config: 512 threads x VPT=2 (16 KB/block, 16384 blocks), 18 regs,
// 32-bit indexing, streaming cache hints.

constexpr int VPT = 2;                 // float4 per thread (32 B/thread)
constexpr int THREADS = 512;
constexpr int TILE = VPT * THREADS;    // float4 per block = 1024 (16 KB)

__global__ void __launch_bounds__(THREADS) fma_stream_kernel(
    const float4* __restrict__ in, float4* __restrict__ out)
{
    unsigned base = blockIdx.x * TILE + threadIdx.x;

    float4 v[VPT];
#pragma unroll
    for (int k = 0; k < VPT; k++)
        v[k] = __ldcs(in + base + k * THREADS);

#pragma unroll
    for (int k = 0; k < VPT; k++) {
        float4 r;
        r.x = fmaf(1.5f, v[k].x, 3.0f);
        r.y = fmaf(1.5f, v[k].y, 3.0f);
        r.z = fmaf(1.5f, v[k].z, 3.0f);
        r.w = fmaf(1.5f, v[k].w, 3.0f);
        __stcs(out + base + k * THREADS, r);
    }
}

// Generic remainder kernel (element granularity, any size).
__global__ void fma_tail_kernel(const float* __restrict__ in,
                                float* __restrict__ out,
                                long long start, long long n)
{
    long long i = start + (long long)blockIdx.x * blockDim.x + threadIdx.x;
    if (i < n) out[i] = fmaf(1.5f, in[i], 3.0f);
}

extern "C" void kernel_launch(void* const* d_in, const int* in_sizes, int n_in,
                              void* d_out, int out_size)
{
    const float* in = (const float*)d_in[0];
    float* out = (float*)d_out;
    long long n = (long long)in_sizes[0];

    long long n4 = n / 4;
    long long full_blocks = n4 / TILE;
    if (full_blocks > 0) {
        fma_stream_kernel<<<(unsigned)full_blocks, THREADS>>>(
            (const float4*)in, (float4*)out);
    }
    long long done = full_blocks * (long long)TILE * 4;  // elements handled
    long long tail = n - done;
    if (tail > 0) {
        fma_tail_kernel<<<(unsigned)((tail + 255) / 256), 256>>>(
            in, out, done, n);
    }
}